// round 4
// baseline (speedup 1.0000x reference)
#include <cuda_runtime.h>
#include <math.h>

// Problem constants
#define BB   8
#define AA   192
#define DD   128
#define RELN 5
#define HH   128
#define EE   (BB*AA*AA)   // 294912 edges

// Scratch (no cudaMalloc allowed)
__device__ float g_pre_i[BB*AA*HH];   // f(i) partial pre-activation
__device__ float g_pre_j[BB*AA*HH];   // f(j) partial pre-activation
__device__ float g_pre_g[BB*HH];      // graph-context partial + b1

// ---------------------------------------------------------------------------
// Precompute pre_i / pre_j:  [1536 x 384] @ W-slices -> [1536 x 256]
// which = tid>>7 selects i-part (W1 rows 0,2D,4D) vs j-part (rows D,3D,5D).
// ---------------------------------------------------------------------------
#define PRE_ROWS 8
__global__ __launch_bounds__(256) void precompute_ij(
    const float* __restrict__ coord, const float* __restrict__ goal,
    const float* __restrict__ frontier, const float* __restrict__ W1)
{
    __shared__ float xs[PRE_ROWS][3*DD];
    const int row0 = blockIdx.x * PRE_ROWS;
    const int tid  = threadIdx.x;

    for (int idx = tid; idx < PRE_ROWS*3*DD; idx += 256) {
        int rr = idx / (3*DD), c = idx % (3*DD);
        int s = c >> 7, d = c & 127;
        const float* src = (s == 0) ? coord : ((s == 1) ? goal : frontier);
        xs[rr][c] = src[(row0 + rr)*DD + d];
    }
    __syncthreads();

    const int which = tid >> 7;    // 0 -> pre_i, 1 -> pre_j
    const int k     = tid & 127;

    float acc[PRE_ROWS];
#pragma unroll
    for (int rr = 0; rr < PRE_ROWS; rr++) acc[rr] = 0.f;

#pragma unroll
    for (int s = 0; s < 3; s++) {
#pragma unroll 4
        for (int d = 0; d < DD; d++) {
            // W1 row: s*2D + which*D + d   (D=128 -> s*256 + which*128 + d)
            float w = W1[(s*256 + which*128 + d)*HH + k];
            int c = s*DD + d;
#pragma unroll
            for (int rr = 0; rr < PRE_ROWS; rr++)
                acc[rr] = fmaf(xs[rr][c], w, acc[rr]);
        }
    }

    float* dst = which ? g_pre_j : g_pre_i;
#pragma unroll
    for (int rr = 0; rr < PRE_ROWS; rr++)
        dst[(row0 + rr)*HH + k] = acc[rr];
}

// ---------------------------------------------------------------------------
// Precompute pre_g[b,k] = b1[k] + sum_d gc[b,d] * W1[6D+REL+d, k]
// ---------------------------------------------------------------------------
__global__ void precompute_g(const float* __restrict__ gc,
                             const float* __restrict__ W1,
                             const float* __restrict__ b1)
{
    __shared__ float gs[DD];
    const int b = blockIdx.x, k = threadIdx.x;
    gs[k] = gc[b*DD + k];
    __syncthreads();
    float acc = b1[k];
#pragma unroll 4
    for (int d = 0; d < DD; d++)
        acc = fmaf(gs[d], W1[(6*DD + RELN + d)*HH + k], acc);
    g_pre_g[b*HH + k] = acc;
}

// ---------------------------------------------------------------------------
// Edge kernel: one block per (b,i). 8 warps, each warp processes one j at a
// time (lane covers 4 H-channels, k = lane + 32*m). Then block softmax.
// ---------------------------------------------------------------------------
__global__ __launch_bounds__(256) void edge_kernel(
    const float* __restrict__ rel,        // [B,A,A,5]
    const int* __restrict__ adj,          // [B,A,A] bool stored as int32
    const float* __restrict__ base,       // [B,A,A]
    const float* __restrict__ W1,
    const float* __restrict__ W2,         // [H,1]
    const float* __restrict__ b2,         // [1]
    float* __restrict__ out)              // [3*E]: weights | score(masked) | learned
{
    const int i = blockIdx.x, b = blockIdx.y;
    const int tid  = threadIdx.x;
    const int wid  = tid >> 5, lane = tid & 31;

    __shared__ float bias_s[HH];       // pre_i + pre_g
    __shared__ float w2_s[HH];
    __shared__ float w1r_s[RELN*HH];
    __shared__ float scores_s[AA];
    __shared__ float red_s[8];
    __shared__ float mx_s, S_s, sum2_s;

    if (tid < HH) {
        bias_s[tid] = g_pre_i[(b*AA + i)*HH + tid] + g_pre_g[b*HH + tid];
        w2_s[tid]   = W2[tid];
    }
    for (int idx = tid; idx < RELN*HH; idx += 256) {
        int r = idx >> 7, k = idx & 127;
        w1r_s[idx] = W1[(6*DD + r)*HH + k];   // rel rows: 6D .. 6D+4
    }
    __syncthreads();

    const float b2v = b2[0];
    const int rowbase = (b*AA + i)*AA;

    for (int j = wid; j < AA; j += 8) {
        const int e = rowbase + j;
        const float* pj = &g_pre_j[(b*AA + j)*HH];
        const float* rf = &rel[(long)e * RELN];
        const float r0 = rf[0], r1 = rf[1], r2 = rf[2], r3 = rf[3], r4 = rf[4];

        float acc = 0.f;
#pragma unroll
        for (int m = 0; m < 4; m++) {
            const int k = lane + 32*m;
            float h = bias_s[k] + pj[k];
            h = fmaf(r0, w1r_s[k],        h);
            h = fmaf(r1, w1r_s[128 + k],  h);
            h = fmaf(r2, w1r_s[256 + k],  h);
            h = fmaf(r3, w1r_s[384 + k],  h);
            h = fmaf(r4, w1r_s[512 + k],  h);
            h = fmaxf(h, 0.f);
            acc = fmaf(h, w2_s[k], acc);
        }
#pragma unroll
        for (int o = 16; o > 0; o >>= 1)
            acc += __shfl_xor_sync(0xffffffffu, acc, o);

        if (lane == 0) {
            const float learned = acc + b2v;
            const float sc = base[e] + learned;
            const float sc_masked = adj[e] ? sc : -1e9f;  // reference returns MASKED score
            out[EE   + e] = sc_masked;   // score (masked)
            out[2*EE + e] = learned;     // learned (unmasked)
            scores_s[j] = sc_masked;
        }
    }
    __syncthreads();

    // ---- softmax over j (replicates reference mask/renorm semantics) ----
    float s = (tid < AA) ? scores_s[tid] : -INFINITY;
#pragma unroll
    for (int o = 16; o > 0; o >>= 1)
        s = fmaxf(s, __shfl_xor_sync(0xffffffffu, s, o));
    if (lane == 0) red_s[wid] = s;
    __syncthreads();
    if (tid == 0) {
        float m = red_s[0];
#pragma unroll
        for (int w = 1; w < 8; w++) m = fmaxf(m, red_s[w]);
        mx_s = m;
    }
    __syncthreads();
    const float mx = mx_s;

    float scv = 0.f, ev = 0.f;
    if (tid < AA) {
        scv = scores_s[tid];
        ev  = expf(scv - mx);   // masked (-1e9) underflows to exactly 0
    }
    float t = ev;
#pragma unroll
    for (int o = 16; o > 0; o >>= 1)
        t += __shfl_xor_sync(0xffffffffu, t, o);
    if (lane == 0) red_s[wid] = t;
    __syncthreads();
    if (tid == 0) {
        float sum = 0.f;
#pragma unroll
        for (int w = 0; w < 8; w++) sum += red_s[w];
        S_s = sum;
    }
    __syncthreads();

    // weights_pre = softmax * adj  (adj flag via -1e9 sentinel)
    float wpre = (tid < AA && scv > -1e8f) ? (ev / S_s) : 0.f;
    t = wpre;
#pragma unroll
    for (int o = 16; o > 0; o >>= 1)
        t += __shfl_xor_sync(0xffffffffu, t, o);
    if (lane == 0) red_s[wid] = t;
    __syncthreads();
    if (tid == 0) {
        float sum = 0.f;
#pragma unroll
        for (int w = 0; w < 8; w++) sum += red_s[w];
        sum2_s = sum;
    }
    __syncthreads();

    if (tid < AA)
        out[rowbase + tid] = wpre / (sum2_s + 1e-8f);
}

// ---------------------------------------------------------------------------
extern "C" void kernel_launch(void* const* d_in, const int* in_sizes, int n_in,
                              void* d_out, int out_size)
{
    const float* coord    = (const float*)d_in[0];
    const float* goal     = (const float*)d_in[1];
    const float* frontier = (const float*)d_in[2];
    const float* rel      = (const float*)d_in[3];
    const int*   adj      = (const int*)d_in[4];
    const float* base     = (const float*)d_in[5];
    const float* gc       = (const float*)d_in[6];
    const float* W1       = (const float*)d_in[7];
    const float* b1       = (const float*)d_in[8];
    const float* W2       = (const float*)d_in[9];
    const float* b2       = (const float*)d_in[10];
    float* out = (float*)d_out;

    precompute_ij<<<(BB*AA)/PRE_ROWS, 256>>>(coord, goal, frontier, W1);
    precompute_g<<<BB, DD>>>(gc, W1, b1);
    dim3 grid(AA, BB);
    edge_kernel<<<grid, 256>>>(rel, adj, base, W1, W2, b2, out);
}